// round 2
// baseline (speedup 1.0000x reference)
#include <cuda_runtime.h>
#include <cfloat>
#include <climits>
#include <cstdint>

// Problem constants
#define NQ    2048      // 4*512 queries
#define NK    65536     // keys/values rows
#define DIM   256
#define TOPK  32

// Tiling
#define TM      32               // queries per CTA  (was 64 -> smem halved -> 2 CTAs/SM)
#define SLICE   2048             // keys per CTA (key-split)
#define CHUNK   128              // keys per staging chunk
#define NSLICES (NK / SLICE)     // 32
#define NQT     (NQ / TM)        // 64
#define NCHUNK  (SLICE / CHUNK)  // 16
#define NKS     (DIM / 16)       // 16 k-slices of 16

// Shared memory layout (floats)
#define BS_ROW 132
#define SS_ROW 134
#define AS_F   (DIM * TM)            // 8192
#define BS_F   (2 * 16 * BS_ROW)     // 4224
#define SS_F   (TM * SS_ROW)         // 4288
#define TV_F   (TM * TOPK)           // 1024
#define SMEM_FLOATS (AS_F + BS_F + SS_F + TV_F + TV_F)
#define SMEM_BYTES  (SMEM_FLOATS * 4)   // 75008 B  -> 2 CTAs/SM

// Partial top-k scratch (device globals: sanctioned scratch, no allocs)
__device__ float g_pv[NQ * NSLICES * TOPK];   // 8 MB
__device__ int   g_pi[NQ * NSLICES * TOPK];   // 8 MB

// ---- Blackwell packed f32x2 helpers --------------------------------------
__device__ __forceinline__ unsigned long long ffma2(unsigned long long a,
                                                    unsigned long long b,
                                                    unsigned long long c) {
    unsigned long long d;
    asm("fma.rn.f32x2 %0, %1, %2, %3;" : "=l"(d) : "l"(a), "l"(b), "l"(c));
    return d;
}
__device__ __forceinline__ unsigned long long pack2(float x) {
    unsigned long long d;
    asm("mov.b64 %0, {%1, %1};" : "=l"(d) : "f"(x));
    return d;
}

// ---- Kernel 1: fused GEMM + per-slice streaming top-32 -------------------
// grid: (NSLICES, NQT), 256 threads, 2 CTAs/SM.
// Thread (r = tid>>5, c = tid&31): queries r*4..r*4+3 vs keys c*4..c*4+3 of
// each 128-key chunk, K fully reduced.
__global__ __launch_bounds__(256, 2)
void score_topk_kernel(const float* __restrict__ query,
                       const float* __restrict__ keys) {
    extern __shared__ float smem[];
    float* As = smem;                 // [DIM][TM]   (d-major, transposed)
    float* Bs = As + AS_F;            // [2][16][BS_ROW]
    float* Ss = Bs + BS_F;            // [TM][SS_ROW]
    float* Tv = Ss + SS_F;            // [TM][TOPK]
    int*   Ti = (int*)(Tv + TV_F);    // [TM][TOPK]

    const int tid = threadIdx.x;
    const int r = tid >> 5;           // warp id, 0..7 -> query group
    const int c = tid & 31;           // lane -> key group

    // --- load the 32x256 query tile once, transposed to As[d][q] ---
    const float* Aq = query + (size_t)blockIdx.y * TM * DIM;
    for (int i = tid; i < TM * (DIM / 4); i += 256) {
        int q  = i >> 6;              // 0..31
        int f4 = i & 63;              // float4 index along d
        float4 v = *(const float4*)(Aq + q * DIM + f4 * 4);
        int d0 = f4 * 4;
        As[(d0 + 0) * TM + q] = v.x;
        As[(d0 + 1) * TM + q] = v.y;
        As[(d0 + 2) * TM + q] = v.z;
        As[(d0 + 3) * TM + q] = v.w;
    }
    // --- init top-k state ---
    for (int i = tid; i < TM * TOPK; i += 256) { Tv[i] = -FLT_MAX; Ti[i] = 0; }
    __syncthreads();

    // per-scanning-thread running min (thread tid<32 owns query tid)
    float minv = -FLT_MAX;
    int   minslot = 0;

    const float* Bbase = keys + (size_t)blockIdx.x * SLICE * DIM;
    const int bkey = tid >> 1;            // 0..127
    const int bd   = (tid & 1) * 8;       // 0 or 8 within 16-wide k-slice

    for (int ch = 0; ch < NCHUNK; ++ch) {
        const float* Bc = Bbase + (size_t)ch * CHUNK * DIM;

        // load k-slice 0 of this chunk into Bs[0]
        {
            float4 u0 = *(const float4*)(Bc + bkey * DIM + bd);
            float4 u1 = *(const float4*)(Bc + bkey * DIM + bd + 4);
            float* Bw = Bs;
            Bw[(bd + 0) * BS_ROW + bkey] = u0.x;
            Bw[(bd + 1) * BS_ROW + bkey] = u0.y;
            Bw[(bd + 2) * BS_ROW + bkey] = u0.z;
            Bw[(bd + 3) * BS_ROW + bkey] = u0.w;
            Bw[(bd + 4) * BS_ROW + bkey] = u1.x;
            Bw[(bd + 5) * BS_ROW + bkey] = u1.y;
            Bw[(bd + 6) * BS_ROW + bkey] = u1.z;
            Bw[(bd + 7) * BS_ROW + bkey] = u1.w;
        }
        __syncthreads();

        // acc[q][j]: j packs keys {c*4+2j, c*4+2j+1}
        unsigned long long acc[4][2];
        #pragma unroll
        for (int i = 0; i < 4; ++i) { acc[i][0] = 0ULL; acc[i][1] = 0ULL; }

        int buf = 0;
        #pragma unroll 1
        for (int ks = 0; ks < NKS; ++ks) {
            float4 n0, n1;
            if (ks < NKS - 1) {
                n0 = *(const float4*)(Bc + bkey * DIM + (ks + 1) * 16 + bd);
                n1 = *(const float4*)(Bc + bkey * DIM + (ks + 1) * 16 + bd + 4);
            }
            const float* Bp = Bs + buf * (16 * BS_ROW);
            const float* Ap = As + ks * 16 * TM;
            #pragma unroll
            for (int kk = 0; kk < 16; ++kk) {
                float4 av = *(const float4*)(Ap + kk * TM + (r << 2));   // warp-uniform (broadcast)
                ulonglong2 b01 = *(const ulonglong2*)(Bp + kk * BS_ROW + (c << 2));
                unsigned long long a0 = pack2(av.x);
                unsigned long long a1 = pack2(av.y);
                unsigned long long a2 = pack2(av.z);
                unsigned long long a3 = pack2(av.w);
                acc[0][0] = ffma2(a0, b01.x, acc[0][0]);
                acc[0][1] = ffma2(a0, b01.y, acc[0][1]);
                acc[1][0] = ffma2(a1, b01.x, acc[1][0]);
                acc[1][1] = ffma2(a1, b01.y, acc[1][1]);
                acc[2][0] = ffma2(a2, b01.x, acc[2][0]);
                acc[2][1] = ffma2(a2, b01.y, acc[2][1]);
                acc[3][0] = ffma2(a3, b01.x, acc[3][0]);
                acc[3][1] = ffma2(a3, b01.y, acc[3][1]);
            }
            if (ks < NKS - 1) {
                float* Bw = Bs + (buf ^ 1) * (16 * BS_ROW);
                Bw[(bd + 0) * BS_ROW + bkey] = n0.x;
                Bw[(bd + 1) * BS_ROW + bkey] = n0.y;
                Bw[(bd + 2) * BS_ROW + bkey] = n0.z;
                Bw[(bd + 3) * BS_ROW + bkey] = n0.w;
                Bw[(bd + 4) * BS_ROW + bkey] = n1.x;
                Bw[(bd + 5) * BS_ROW + bkey] = n1.y;
                Bw[(bd + 6) * BS_ROW + bkey] = n1.z;
                Bw[(bd + 7) * BS_ROW + bkey] = n1.w;
            }
            __syncthreads();
            buf ^= 1;
        }

        // --- stage chunk scores to smem (packed 8B stores) ---
        #pragma unroll
        for (int i = 0; i < 4; ++i) {
            int q = (r << 2) + i;
            float* row = Ss + q * SS_ROW;
            *(unsigned long long*)(row + (c << 2))     = acc[i][0];
            *(unsigned long long*)(row + (c << 2) + 2) = acc[i][1];
        }
        __syncthreads();

        // --- streaming top-32 update: thread q scans its 128 chunk scores ---
        if (tid < TM) {
            const int q = tid;
            const int gbase = blockIdx.x * SLICE + ch * CHUNK;
            const float* srow = Ss + q * SS_ROW;
            float* Trow = Tv + q * TOPK;
            int*   Irow = Ti + q * TOPK;
            for (int k = 0; k < CHUNK; ++k) {
                float s = srow[k];
                if (s > minv) {
                    Trow[minslot] = s;
                    Irow[minslot] = gbase + k;
                    // rescan for new min
                    float m = Trow[0]; int ms = 0;
                    #pragma unroll
                    for (int j = 1; j < TOPK; ++j) {
                        float v = Trow[j];
                        if (v < m) { m = v; ms = j; }
                    }
                    minv = m; minslot = ms;
                }
            }
        }
        __syncthreads();
    }

    // --- write per-slice partial top-32 to global ---
    const int qt = blockIdx.y * TM;
    for (int i = tid; i < TM * TOPK; i += 256) {
        int q = i >> 5, j = i & 31;
        size_t off = (((size_t)(qt + q)) * NSLICES + blockIdx.x) * TOPK + j;
        g_pv[off] = Tv[q * TOPK + j];
        g_pi[off] = Ti[q * TOPK + j];
    }
}

// ---- Kernel 2: merge partials, softmax, gather values --------------------
// grid: NQ CTAs, 256 threads (one thread per output dim).
__global__ __launch_bounds__(256)
void topk_merge_kernel(const float* __restrict__ vals,
                       float* __restrict__ out) {
    __shared__ float cv[NSLICES * TOPK];   // 1024 candidates
    __shared__ int   ci[NSLICES * TOPK];
    __shared__ float redv[256];
    __shared__ int   redi[256];
    __shared__ int   redp[256];
    __shared__ float sscore[TOPK];
    __shared__ int   sidx[TOPK];
    __shared__ float wts[TOPK];

    const int q = blockIdx.x;
    const int tid = threadIdx.x;

    for (int i = tid; i < NSLICES * TOPK; i += 256) {
        cv[i] = g_pv[(size_t)q * (NSLICES * TOPK) + i];
        ci[i] = g_pi[(size_t)q * (NSLICES * TOPK) + i];
    }
    __syncthreads();

    // exact top-32 of the 1024 candidates (tie-break: lower key index)
    for (int it = 0; it < TOPK; ++it) {
        float bv = -FLT_MAX; int bi = INT_MAX; int bp = 0;
        for (int i = tid; i < NSLICES * TOPK; i += 256) {
            float v = cv[i]; int ii = ci[i];
            if (v > bv || (v == bv && ii < bi)) { bv = v; bi = ii; bp = i; }
        }
        redv[tid] = bv; redi[tid] = bi; redp[tid] = bp;
        __syncthreads();
        for (int s = 128; s > 0; s >>= 1) {
            if (tid < s) {
                float ov = redv[tid + s]; int oi = redi[tid + s];
                if (ov > redv[tid] || (ov == redv[tid] && oi < redi[tid])) {
                    redv[tid] = ov; redi[tid] = oi; redp[tid] = redp[tid + s];
                }
            }
            __syncthreads();
        }
        if (tid == 0) {
            int p = redp[0];
            sscore[it] = cv[p];
            sidx[it]   = ci[p];
            cv[p] = -FLT_MAX;
        }
        __syncthreads();
    }

    // softmax over the 32 selected (scaled) scores — warp 0
    if (tid < 32) {
        float s = sscore[tid] * 0.0625f;   // D_MODEL^-0.5
        float m = s;
        #pragma unroll
        for (int o = 16; o > 0; o >>= 1) m = fmaxf(m, __shfl_xor_sync(0xffffffffu, m, o));
        float e = expf(s - m);
        float sum = e;
        #pragma unroll
        for (int o = 16; o > 0; o >>= 1) sum += __shfl_xor_sync(0xffffffffu, sum, o);
        wts[tid] = e / sum;
    }
    __syncthreads();

    // gather + weighted sum: thread = one output dim
    const int d = tid;
    float acc = 0.0f;
    #pragma unroll 8
    for (int j = 0; j < TOPK; ++j) {
        acc += wts[j] * __ldg(vals + (size_t)sidx[j] * DIM + d);
    }
    out[(size_t)q * DIM + d] = acc;
}

// ---- Host launch ---------------------------------------------------------
extern "C" void kernel_launch(void* const* d_in, const int* in_sizes, int n_in,
                              void* d_out, int out_size) {
    const float* query = (const float*)d_in[0];   // [4,512,256]
    const float* keys  = (const float*)d_in[1];   // [65536,256]
    const float* vals  = (const float*)d_in[2];   // [65536,256]
    float* out = (float*)d_out;                   // [4,512,256]

    cudaFuncSetAttribute(score_topk_kernel,
                         cudaFuncAttributeMaxDynamicSharedMemorySize, SMEM_BYTES);

    dim3 grid1(NSLICES, NQT);
    score_topk_kernel<<<grid1, 256, SMEM_BYTES>>>(query, keys);
    topk_merge_kernel<<<NQ, 256>>>(vals, out);
}

// round 6
// speedup vs baseline: 5.8518x; 5.8518x over previous
#include <cuda_runtime.h>
#include <cuda_bf16.h>
#include <cfloat>
#include <climits>
#include <cstdint>

// ---------------- problem constants ----------------
#define NQ    2048
#define NK    65536
#define DIM   256
#define TOPK  32

// kernel-1 tiling
#define QT     128               // queries per CTA
#define NQT    (NQ / QT)         // 16
#define NSL    64                // key slices
#define SLKEYS (NK / NSL)        // 1024 keys per slice
#define TN     32                // keys per tile
#define NTILE  (SLKEYS / TN)     // 32
#define KPQ    12                // candidates kept per (query, slice)
#define KPQS   13
#define NCAND  (NSL * KPQ)       // 768 per query
#define NRES   48                // exact-rescored candidates

#define BROW   264               // Bs row stride in bf16 (528 B, conflict-free LDSM)
#define SROW   34                // Ss row stride in floats (even -> 8B-aligned float2)

// ---------------- device scratch (globals, no allocs) ----------------
__device__ __nv_bfloat16 g_kb[(size_t)NK * DIM];   // 32 MB bf16 keys
__device__ float g_pv[(size_t)NQ * NCAND];         // 6 MB
__device__ int   g_pi[(size_t)NQ * NCAND];         // 6 MB

// ---------------- PTX helpers (base sm_103 ISA only) ----------------
__device__ __forceinline__ uint32_t smem_u32(const void* p) {
    uint32_t a;
    asm("{ .reg .u64 t; cvta.to.shared.u64 t, %1; cvt.u32.u64 %0, t; }" : "=r"(a) : "l"(p));
    return a;
}

// NON-trans: lane l gets stored-row l/4 (key), two consecutive stored cols (dims)
#define LDSM4(r, addr) \
    asm volatile("ldmatrix.sync.aligned.m8n8.x4.shared.b16 {%0,%1,%2,%3}, [%4];" \
        : "=r"((r)[0]), "=r"((r)[1]), "=r"((r)[2]), "=r"((r)[3]) : "r"(addr))

#define MMA16816(d, A, b0, b1) \
    asm volatile("mma.sync.aligned.m16n8k16.row.col.f32.bf16.bf16.f32 " \
        "{%0,%1,%2,%3}, {%4,%5,%6,%7}, {%8,%9}, {%0,%1,%2,%3};" \
        : "+f"((d)[0]), "+f"((d)[1]), "+f"((d)[2]), "+f"((d)[3]) \
        : "r"((A)[0]), "r"((A)[1]), "r"((A)[2]), "r"((A)[3]), "r"(b0), "r"(b1))

// ---------------- kernel 0: keys fp32 -> bf16 ----------------
__global__ __launch_bounds__(256)
void convert_keys_kernel(const float* __restrict__ keys) {
    size_t idx = ((size_t)blockIdx.x * 256 + threadIdx.x) * 8;
    float4 a = *(const float4*)(keys + idx);
    float4 b = *(const float4*)(keys + idx + 4);
    __nv_bfloat162 p0 = __float22bfloat162_rn(make_float2(a.x, a.y));
    __nv_bfloat162 p1 = __float22bfloat162_rn(make_float2(a.z, a.w));
    __nv_bfloat162 p2 = __float22bfloat162_rn(make_float2(b.x, b.y));
    __nv_bfloat162 p3 = __float22bfloat162_rn(make_float2(b.z, b.w));
    uint4 o;
    o.x = *(uint32_t*)&p0; o.y = *(uint32_t*)&p1;
    o.z = *(uint32_t*)&p2; o.w = *(uint32_t*)&p3;
    *(uint4*)(g_kb + idx) = o;
}

// ---------------- kernel 1: HMMA bf16 scores + streaming per-slice top-12 ---
// 128 threads (4 warps). Warp w owns queries [w*32, w*32+32) of the CTA's 128.
__global__ __launch_bounds__(128, 2)
void score_topk_kernel(const float* __restrict__ query) {
    __shared__ __align__(16) __nv_bfloat16 Bs[TN * BROW];   // 16.9 KB
    __shared__ __align__(16) float Ss[QT * SROW];           // 17.4 KB
    __shared__ float Tv[QT * KPQS];                         // 6.7 KB
    __shared__ int   Ti[QT * KPQS];                         // 6.7 KB

    const int tid  = threadIdx.x;
    const int wid  = tid >> 5;
    const int lane = tid & 31;
    const int slice = blockIdx.x;
    const int qb    = blockIdx.y * QT;

    // ---- load persistent A fragments (fp32 -> bf16 cvt in flight) ----
    uint32_t a[2][16][4];
    {
        const int tq = lane >> 2;
        const int tk = (lane & 3) * 2;
        #pragma unroll
        for (int mb = 0; mb < 2; ++mb) {
            const float* b0 = query + (size_t)(qb + wid * 32 + mb * 16 + tq) * DIM;
            const float* b1 = b0 + 8 * DIM;
            #pragma unroll
            for (int ks = 0; ks < 16; ++ks) {
                float2 f0 = *(const float2*)(b0 + ks * 16 + tk);
                float2 f1 = *(const float2*)(b1 + ks * 16 + tk);
                float2 f2 = *(const float2*)(b0 + ks * 16 + tk + 8);
                float2 f3 = *(const float2*)(b1 + ks * 16 + tk + 8);
                __nv_bfloat162 p0 = __float22bfloat162_rn(f0);
                __nv_bfloat162 p1 = __float22bfloat162_rn(f1);
                __nv_bfloat162 p2 = __float22bfloat162_rn(f2);
                __nv_bfloat162 p3 = __float22bfloat162_rn(f3);
                a[mb][ks][0] = *(uint32_t*)&p0;
                a[mb][ks][1] = *(uint32_t*)&p1;
                a[mb][ks][2] = *(uint32_t*)&p2;
                a[mb][ks][3] = *(uint32_t*)&p3;
            }
        }
    }

    // ---- top-k state (thread tid owns query tid) ----
    #pragma unroll
    for (int j = 0; j < KPQ; ++j) { Tv[tid * KPQS + j] = -FLT_MAX; Ti[tid * KPQS + j] = 0; }
    float minv = -FLT_MAX;
    int   minslot = 0;

    // ---- ldmatrix lane base addresses (non-trans x4) ----
    // m0: keys 0-7 / dims 0-7, m1: keys 0-7 / dims 8-15,
    // m2: keys 8-15 / dims 0-7, m3: keys 8-15 / dims 8-15
    const uint32_t bs_base = smem_u32(Bs);
    const int keyA = ((lane >> 4) & 1) * 8 + (lane & 7);
    const uint32_t ld0 = bs_base + (uint32_t)keyA * (BROW * 2) + (((lane >> 3) & 1) * 16);
    const uint32_t ld1 = ld0 + 16u * (BROW * 2);     // keys +16 (n-tiles 2,3)

    const int sq0 = wid * 32 + (lane >> 2);
    const int sk0 = (lane & 3) * 2;

    #pragma unroll 1
    for (int t = 0; t < NTILE; ++t) {
        // ---- stage 32 keys x 256 dims bf16 into Bs ----
        const __nv_bfloat16* kb = g_kb + ((size_t)slice * SLKEYS + (size_t)t * TN) * DIM;
        #pragma unroll
        for (int j = 0; j < 8; ++j) {
            int seg = tid + 128 * j;
            int key = seg >> 5, inr = seg & 31;
            uint4 v = *(const uint4*)(kb + key * DIM + inr * 8);
            *(uint4*)((char*)Bs + key * (BROW * 2) + inr * 16) = v;
        }
        __syncthreads();

        // ---- MMA: 2 m-blocks x 4 n-tiles x 16 k-steps ----
        float c[2][4][4];
        #pragma unroll
        for (int mb = 0; mb < 2; ++mb)
            #pragma unroll
            for (int nt = 0; nt < 4; ++nt)
                #pragma unroll
                for (int e = 0; e < 4; ++e) c[mb][nt][e] = 0.0f;

        #pragma unroll
        for (int ks = 0; ks < 16; ++ks) {
            uint32_t b[8];
            LDSM4(b,     ld0 + ks * 32);   // b0,b1 = nt0; b2,b3 = nt1
            LDSM4(b + 4, ld1 + ks * 32);   // b4,b5 = nt2; b6,b7 = nt3
            #pragma unroll
            for (int mb = 0; mb < 2; ++mb) {
                MMA16816(c[mb][0], a[mb][ks], b[0], b[1]);
                MMA16816(c[mb][1], a[mb][ks], b[2], b[3]);
                MMA16816(c[mb][2], a[mb][ks], b[4], b[5]);
                MMA16816(c[mb][3], a[mb][ks], b[6], b[7]);
            }
        }

        // ---- D frags -> Ss (scores for this warp's 32 queries) ----
        #pragma unroll
        for (int mb = 0; mb < 2; ++mb) {
            #pragma unroll
            for (int nt = 0; nt < 4; ++nt) {
                int q = sq0 + mb * 16;
                int k = nt * 8 + sk0;
                *(float2*)&Ss[q * SROW + k]       = make_float2(c[mb][nt][0], c[mb][nt][1]);
                *(float2*)&Ss[(q + 8) * SROW + k] = make_float2(c[mb][nt][2], c[mb][nt][3]);
            }
        }
        __syncwarp();

        // ---- streaming top-12: thread tid scans its query's 32 scores ----
        {
            const float* srow = Ss + tid * SROW;
            const int base = slice * SLKEYS + t * TN;
            float* Tr = Tv + tid * KPQS;
            int*   Ir = Ti + tid * KPQS;
            #pragma unroll
            for (int k = 0; k < TN; ++k) {
                float s = srow[k];
                if (s > minv) {
                    Tr[minslot] = s; Ir[minslot] = base + k;
                    float m = Tr[0]; int ms = 0;
                    #pragma unroll
                    for (int j = 1; j < KPQ; ++j) {
                        float u = Tr[j];
                        if (u < m) { m = u; ms = j; }
                    }
                    minv = m; minslot = ms;
                }
            }
        }
        __syncthreads();
    }

    // ---- write per-slice candidates ----
    const size_t qg = (size_t)qb + tid;
    #pragma unroll
    for (int j = 0; j < KPQ; ++j) {
        g_pv[qg * NCAND + slice * KPQ + j] = Tv[tid * KPQS + j];
        g_pi[qg * NCAND + slice * KPQ + j] = Ti[tid * KPQS + j];
    }
}

// ---------------- kernel 2: merge + exact fp32 rescore + softmax + gather ---
__device__ __forceinline__ void amax3(float& v, int& i, int& p, float v2, int i2, int p2) {
    if (v2 > v || (v2 == v && i2 < i)) { v = v2; i = i2; p = p2; }
}

__global__ __launch_bounds__(256)
void merge_kernel(const float* __restrict__ query,
                  const float* __restrict__ keys,
                  const float* __restrict__ vals,
                  float* __restrict__ out) {
    __shared__ float cv[NCAND];
    __shared__ int   ci[NCAND];
    __shared__ float redv[8];
    __shared__ int   redi[8], redp[8];
    __shared__ int   candIdx[NRES];
    __shared__ float qrow[DIM];
    __shared__ float rs[NRES];
    __shared__ float selv[TOPK];
    __shared__ int   seli[TOPK];
    __shared__ float wts[TOPK];

    const int q = blockIdx.x;
    const int tid = threadIdx.x;
    const int w = tid >> 5, lane = tid & 31;

    for (int i = tid; i < NCAND; i += 256) {
        cv[i] = g_pv[(size_t)q * NCAND + i];
        ci[i] = g_pi[(size_t)q * NCAND + i];
    }
    qrow[tid] = query[(size_t)q * DIM + tid];
    __syncthreads();

    // --- approx top-48 (destructive argmax; tie-break lower key index) ---
    for (int it = 0; it < NRES; ++it) {
        float bv = -FLT_MAX; int bi = INT_MAX, bp = 0;
        #pragma unroll
        for (int r = 0; r < NCAND / 256; ++r) {
            int i = tid + r * 256;
            amax3(bv, bi, bp, cv[i], ci[i], i);
        }
        #pragma unroll
        for (int o = 16; o > 0; o >>= 1) {
            float ov = __shfl_xor_sync(0xffffffffu, bv, o);
            int oi = __shfl_xor_sync(0xffffffffu, bi, o);
            int op = __shfl_xor_sync(0xffffffffu, bp, o);
            amax3(bv, bi, bp, ov, oi, op);
        }
        if (lane == 0) { redv[w] = bv; redi[w] = bi; redp[w] = bp; }
        __syncthreads();
        if (tid == 0) {
            float fv = redv[0]; int fi = redi[0], fp = redp[0];
            #pragma unroll
            for (int k = 1; k < 8; ++k) amax3(fv, fi, fp, redv[k], redi[k], redp[k]);
            candIdx[it] = fi;
            cv[fp] = -FLT_MAX;
        }
        __syncthreads();
    }

    // --- exact fp32 rescore of the 48 candidates (6 per warp) ---
    #pragma unroll
    for (int r = 0; r < NRES / 8; ++r) {
        int j = w * (NRES / 8) + r;
        const float* kr = keys + (size_t)candIdx[j] * DIM;
        float acc = 0.0f;
        #pragma unroll
        for (int d = 0; d < DIM / 32; ++d)
            acc = fmaf(qrow[lane + d * 32], kr[lane + d * 32], acc);
        #pragma unroll
        for (int o = 16; o > 0; o >>= 1) acc += __shfl_xor_sync(0xffffffffu, acc, o);
        if (lane == 0) rs[j] = acc;
    }
    __syncthreads();

    // --- exact top-32 of the 48 rescored (warp 0; jax tie-break) ---
    if (w == 0) {
        for (int it = 0; it < TOPK; ++it) {
            float bv = rs[lane]; int bi = candIdx[lane], bp = lane;
            if (lane < NRES - 32) amax3(bv, bi, bp, rs[lane + 32], candIdx[lane + 32], lane + 32);
            #pragma unroll
            for (int o = 16; o > 0; o >>= 1) {
                float ov = __shfl_xor_sync(0xffffffffu, bv, o);
                int oi = __shfl_xor_sync(0xffffffffu, bi, o);
                int op = __shfl_xor_sync(0xffffffffu, bp, o);
                amax3(bv, bi, bp, ov, oi, op);
            }
            if (lane == 0) { selv[it] = bv; seli[it] = bi; rs[bp] = -FLT_MAX; }
            __syncwarp();
        }
        float s = selv[lane] * 0.0625f;   // D_MODEL^-0.5
        float m = s;
        #pragma unroll
        for (int o = 16; o > 0; o >>= 1) m = fmaxf(m, __shfl_xor_sync(0xffffffffu, m, o));
        float e = expf(s - m);
        float sum = e;
        #pragma unroll
        for (int o = 16; o > 0; o >>= 1) sum += __shfl_xor_sync(0xffffffffu, sum, o);
        wts[lane] = e / sum;
    }
    __syncthreads();

    // --- gather + weighted sum (thread = output dim) ---
    const int d = tid;
    float acc = 0.0f;
    #pragma unroll 8
    for (int j = 0; j < TOPK; ++j)
        acc += wts[j] * __ldg(vals + (size_t)seli[j] * DIM + d);
    out[(size_t)q * DIM + d] = acc;
}

// ---------------- host launch ----------------
extern "C" void kernel_launch(void* const* d_in, const int* in_sizes, int n_in,
                              void* d_out, int out_size) {
    const float* query = (const float*)d_in[0];   // [4,512,256]
    const float* keys  = (const float*)d_in[1];   // [65536,256]
    const float* vals  = (const float*)d_in[2];   // [65536,256]
    float* out = (float*)d_out;

    convert_keys_kernel<<<(NK * DIM) / (256 * 8), 256>>>(keys);
    score_topk_kernel<<<dim3(NSL, NQT), 128>>>(query);
    merge_kernel<<<NQ, 256>>>(query, keys, vals, out);
}